// round 6
// baseline (speedup 1.0000x reference)
#include <cuda_runtime.h>
#include <math.h>

#define RR 273
#define CC 256
#define KK 219
#define NTHREADS 256
#define SORTN 512
#define NWARPS 8
#define HB 280          // per-warp histogram stride (>= RR)
#define FULLM 0xFFFFFFFFu

__device__ int g_edge_is64;

__global__ void probe_dtype_kernel(const int* ei32) {
    if (threadIdx.x == 0) {
        int all_zero = 1;
        #pragma unroll
        for (int i = 1; i < 64; i += 2)
            if (ei32[i] != 0) { all_zero = 0; break; }
        g_edge_is64 = all_zero;
    }
}

__device__ __forceinline__ unsigned int ord_f32(float f) {
    unsigned int u = __float_as_uint(f);
    return (u & 0x80000000u) ? ~u : (u | 0x80000000u);
}

__global__ __launch_bounds__(NTHREADS, 2)
void sagpool_kernel(const float* __restrict__ x,
                    const void*  __restrict__ edge_index,
                    const float* __restrict__ Wp,
                    const float* __restrict__ bp,
                    float* __restrict__ out,
                    long long E, int epg,
                    size_t off_ei, size_t off_keep, size_t off_batch,
                    size_t off_perm, size_t off_score)
{
    extern __shared__ char smem[];
    // ---- layout (must match host sizing) ----
    float* wsh   = (float*)smem;                       // 256
    float* h_s   = wsh + CC;                           // 288
    float* dis_s = h_s + 288;                          // 288
    float* sc_s  = dis_s + 288;                        // 288
    int* indeg_s = (int*)(sc_s + 288);                 // 288
    int* start_s = indeg_s + 288;                      // 288
    int* newid_s = start_s + 288;                      // 288
    unsigned long long* keys = (unsigned long long*)(newid_s + 288); // 512
    unsigned int* ed = (unsigned int*)(keys + SORTN);  // epg u32
    char* ubase = (char*)(ed + epg);                   // union region
    float* xt = (float*)ubase;                         // [RR][33]
    unsigned short* ssrc = (unsigned short*)ubase;     // epg u16
    int* hist = (int*)(ubase + (((size_t)epg * 2 + 15) & ~(size_t)15)); // 8*HB

    const int tid  = threadIdx.x;
    const int lane = tid & 31;
    const int warp = tid >> 5;
    const int g    = blockIdx.x;
    const long long gbase = (long long)g * RR;
    const int is64 = g_edge_is64;

    // ---- stage W, init small arrays ----
    if (tid < CC) wsh[tid] = Wp[tid];
    for (int v = tid; v < RR; v += NTHREADS) newid_s[v] = -1;
    __syncthreads();

    // ---- phase A: h[v] as Eigen NEON row-major gemv (evalGemv path):
    //      one 4-lane packet accumulator, pmadd = vfmaq (fused FMA),
    //      predux: sum=(a0+a2, a1+a3); result=(a0+a2)+(a1+a3)
    {
        float a00 = 0.f, a01 = 0.f, a02 = 0.f, a03 = 0.f;   // row tid
        float a10 = 0.f, a11 = 0.f, a12 = 0.f, a13 = 0.f;   // row tid+256
        for (int kc = 0; kc < CC; kc += 32) {
            for (int idx = tid; idx < RR * 8; idx += NTHREADS) {
                int r = idx >> 3, q = idx & 7;
                float4 a = *(const float4*)(x + ((size_t)(gbase + r)) * CC + kc + q * 4);
                float* dp = &xt[r * 33 + q * 4];
                dp[0] = a.x; dp[1] = a.y; dp[2] = a.z; dp[3] = a.w;
            }
            __syncthreads();
            if (tid < RR) {
                const float* row = &xt[tid * 33];
                #pragma unroll
                for (int q = 0; q < 8; q++) {
                    a00 = fmaf(row[4*q+0], wsh[kc+4*q+0], a00);
                    a01 = fmaf(row[4*q+1], wsh[kc+4*q+1], a01);
                    a02 = fmaf(row[4*q+2], wsh[kc+4*q+2], a02);
                    a03 = fmaf(row[4*q+3], wsh[kc+4*q+3], a03);
                }
            }
            int v1 = tid + NTHREADS;
            if (v1 < RR) {
                const float* row = &xt[v1 * 33];
                #pragma unroll
                for (int q = 0; q < 8; q++) {
                    a10 = fmaf(row[4*q+0], wsh[kc+4*q+0], a10);
                    a11 = fmaf(row[4*q+1], wsh[kc+4*q+1], a11);
                    a12 = fmaf(row[4*q+2], wsh[kc+4*q+2], a12);
                    a13 = fmaf(row[4*q+3], wsh[kc+4*q+3], a13);
                }
            }
            __syncthreads();
        }
        // Eigen predux: (a0+a2)+(a1+a3)
        if (tid < RR)
            h_s[tid] = __fadd_rn(__fadd_rn(a00, a02), __fadd_rn(a01, a03));
        if (tid + NTHREADS < RR)
            h_s[tid + NTHREADS] = __fadd_rn(__fadd_rn(a10, a12), __fadd_rn(a11, a13));
    }

    // ---- load edges -> packed local ids (src<<16 | dst) ----
    {
        const long long ebase = (long long)g * epg;
        if (is64) {
            const long long* p = (const long long*)edge_index;
            for (int e = tid; e < epg; e += NTHREADS) {
                int ls = (int)(p[ebase + e] - gbase);
                int ld = (int)(p[ebase + E + e] - gbase);
                ed[e] = ((unsigned)ls << 16) | (unsigned)ld;
            }
        } else {
            const int* p = (const int*)edge_index;
            for (int e = tid; e < epg; e += NTHREADS) {
                int ls = (int)(p[ebase + e] - gbase);
                int ld = (int)(p[ebase + E + e] - gbase);
                ed[e] = ((unsigned)ls << 16) | (unsigned)ld;
            }
        }
    }
    __syncthreads();   // h done (xt free), ed ready

    // ---- stable counting sort of edges by dst ----
    for (int i = tid; i < NWARPS * HB; i += NTHREADS) hist[i] = 0;
    __syncthreads();

    const int per = (((epg + NWARPS - 1) / NWARPS) + 31) & ~31;
    const int cbeg = warp * per;
    const int cend = min(epg, cbeg + per);

    // pass 1: per-warp-chunk histograms
    for (int base = cbeg; base < cend; base += 32) {
        int e = base + lane;
        bool act = e < cend;
        unsigned v = act ? ed[e] : 0u;
        int dst = act ? (int)(v & 0xFFFFu) : (512 + lane);
        unsigned m = __match_any_sync(FULLM, dst);
        int leader = __ffs(m) - 1;
        if (act && lane == leader) hist[warp * HB + dst] += __popc(m);
        __syncwarp();
    }
    __syncthreads();

    // in-degree, dis = 1/sqrt(deg) (deg includes self-loop), both correctly rounded
    for (int v = tid; v < RR; v += NTHREADS) {
        int s = 0;
        #pragma unroll
        for (int w2 = 0; w2 < NWARPS; w2++) s += hist[w2 * HB + v];
        indeg_s[v] = s;
        dis_s[v] = __fdiv_rn(1.0f, __fsqrt_rn((float)(s + 1)));
    }
    __syncthreads();

    // exclusive scan of indeg -> start offsets (warp 0)
    if (warp == 0) {
        int lo = lane * 9;
        int acc = 0;
        #pragma unroll
        for (int i = 0; i < 9; i++) { int v = lo + i; if (v < RR) acc += indeg_s[v]; }
        int ex = acc;
        #pragma unroll
        for (int o = 1; o < 32; o <<= 1) {
            int t = __shfl_up_sync(FULLM, ex, o);
            if (lane >= o) ex += t;
        }
        ex -= acc;
        int run = ex;
        #pragma unroll
        for (int i = 0; i < 9; i++) {
            int v = lo + i;
            if (v < RR) { start_s[v] = run; run += indeg_s[v]; }
        }
    }
    __syncthreads();

    // per-(warp,dst) base pointers (in place)
    for (int v = tid; v < RR; v += NTHREADS) {
        int s = start_s[v];
        #pragma unroll
        for (int w2 = 0; w2 < NWARPS; w2++) {
            int t = hist[w2 * HB + v];
            hist[w2 * HB + v] = s;
            s += t;
        }
    }
    __syncthreads();

    // pass 2: stable placement of src ids into per-dst lists
    for (int base = cbeg; base < cend; base += 32) {
        int e = base + lane;
        bool act = e < cend;
        unsigned v = act ? ed[e] : 0u;
        int dst = act ? (int)(v & 0xFFFFu) : (512 + lane);
        unsigned m = __match_any_sync(FULLM, dst);
        int rank = __popc(m & ((1u << lane) - 1u));
        int pos = 0;
        if (act) pos = hist[warp * HB + dst] + rank;
        __syncwarp();
        if (act) ssrc[pos] = (unsigned short)(v >> 16);
        int leader = __ffs(m) - 1;
        if (act && lane == leader) hist[warp * HB + dst] += __popc(m);
        __syncwarp();
    }
    __syncthreads();

    // ---- score: strictly sequential in reference scatter order ----
    const float bval = bp[0];
    for (int v = tid; v < RR; v += NTHREADS) {
        float dv = dis_s[v];
        float acc = 0.f;
        int st = start_s[v], n = indeg_s[v];
        for (int i = 0; i < n; i++) {
            int src = ssrc[st + i];
            float c = __fmul_rn(__fmul_rn(dis_s[src], dv), h_s[src]);
            acc = __fadd_rn(acc, c);
        }
        float selfc = __fmul_rn(__fmul_rn(dv, dv), h_s[v]);
        acc = __fadd_rn(acc, selfc);
        float sc = __fadd_rn(acc, bval);
        sc_s[v] = sc;
        out[off_score + (size_t)gbase + v] = sc;
    }
    __syncthreads();

    // ---- sort keys ----
    for (int v = tid; v < SORTN; v += NTHREADS) {
        if (v < RR) {
            keys[v] = ((unsigned long long)ord_f32(sc_s[v]) << 32)
                      | (unsigned long long)(0x1FFu - (unsigned)v);
        } else keys[v] = 0ull;
    }

    // bitonic sort descending (ties -> lower index first)
    for (int kk = 2; kk <= SORTN; kk <<= 1) {
        for (int j = kk >> 1; j > 0; j >>= 1) {
            __syncthreads();
            for (int t = tid; t < SORTN; t += NTHREADS) {
                int ixj = t ^ j;
                if (ixj > t) {
                    bool desc = ((t & kk) == 0);
                    unsigned long long a = keys[t], b2 = keys[ixj];
                    if ((a < b2) == desc) { keys[t] = b2; keys[ixj] = a; }
                }
            }
        }
    }
    __syncthreads();

    // ---- new-id map ----
    if (tid < KK) {
        int v = 0x1FF - (int)(keys[tid] & 0xFFFFFFFFull);
        newid_s[v] = tid;
    }
    __syncthreads();

    // ---- x_new / perm / batch_new ----
    for (int k = warp; k < KK; k += NWARPS) {
        int v = 0x1FF - (int)(keys[k] & 0xFFFFFFFFull);
        float t = tanhf(sc_s[v]);
        const float4* srcp = (const float4*)(x + ((size_t)(gbase + v)) * CC);
        float4* dstp = (float4*)(out + ((size_t)g * KK + k) * CC);
        #pragma unroll
        for (int j = 0; j < 2; j++) {
            float4 a = srcp[lane + 32 * j];
            a.x *= t; a.y *= t; a.z *= t; a.w *= t;
            dstp[lane + 32 * j] = a;
        }
        if (lane == 0) {
            out[off_perm  + (size_t)g * KK + k] = (float)(gbase + v);
            out[off_batch + (size_t)g * KK + k] = (float)g;
        }
    }

    // ---- edge remap + keep ----
    {
        const size_t ebase = (size_t)g * epg;
        const int gk = g * KK;
        for (int e = tid; e < epg; e += NTHREADS) {
            unsigned v = ed[e];
            int ns = newid_s[v >> 16];
            int nd = newid_s[v & 0xFFFFu];
            size_t ge = ebase + e;
            if (ns >= 0 && nd >= 0) {
                out[off_ei + ge]             = (float)(gk + ns);
                out[off_ei + (size_t)E + ge] = (float)(gk + nd);
                out[off_keep + ge]           = 1.0f;
            } else {
                out[off_ei + ge]             = -1.0f;
                out[off_ei + (size_t)E + ge] = -1.0f;
                out[off_keep + ge]           = 0.0f;
            }
        }
    }
}

extern "C" void kernel_launch(void* const* d_in, const int* in_sizes, int n_in,
                              void* d_out, int out_size)
{
    const float* x  = (const float*)d_in[0];
    const void*  ei = d_in[1];
    const float* W  = (const float*)d_in[3];
    const float* b  = (const float*)d_in[4];

    long long N = (long long)in_sizes[0] / CC;
    long long E = (long long)in_sizes[1] / 2;
    int G   = (int)(N / RR);
    int epg = (int)(E / G);

    float* out = (float*)d_out;
    size_t GK        = (size_t)G * KK;
    size_t off_ei    = GK * CC;
    size_t off_keep  = off_ei + 2 * (size_t)E;
    size_t off_batch = off_keep + (size_t)E;
    size_t off_perm  = off_batch + GK;
    size_t off_score = off_perm + GK;

    // dynamic smem size (must match kernel layout)
    size_t fixed = (size_t)CC * 4 + 3 * 288 * 4 + 3 * 288 * 4 + (size_t)SORTN * 8;
    size_t edB   = (size_t)epg * 4;
    size_t sortB = (((size_t)epg * 2 + 15) & ~(size_t)15) + (size_t)NWARPS * HB * 4;
    size_t xtB   = (size_t)RR * 33 * 4;
    size_t uB    = sortB > xtB ? sortB : xtB;
    size_t smemB = fixed + edB + uB + 64;

    static int attr_set = 0;
    if (!attr_set) {
        cudaFuncSetAttribute(sagpool_kernel,
                             cudaFuncAttributeMaxDynamicSharedMemorySize,
                             (int)smemB);
        attr_set = 1;
    }

    probe_dtype_kernel<<<1, 32>>>((const int*)ei);
    sagpool_kernel<<<G, NTHREADS, smemB>>>(x, ei, W, b, out, E, epg,
                                           off_ei, off_keep, off_batch,
                                           off_perm, off_score);
}

// round 7
// speedup vs baseline: 1.0983x; 1.0983x over previous
#include <cuda_runtime.h>
#include <math.h>

#define RR 273
#define CC 256
#define KK 219
#define NTHREADS 256
#define SORTN 512
#define NWARPS 8
#define HB 280          // per-warp histogram stride (>= RR)
#define FULLM 0xFFFFFFFFu

__device__ int g_edge_is64;

__global__ void probe_dtype_kernel(const int* ei32) {
    if (threadIdx.x == 0) {
        int all_zero = 1;
        #pragma unroll
        for (int i = 1; i < 64; i += 2)
            if (ei32[i] != 0) { all_zero = 0; break; }
        g_edge_is64 = all_zero;
    }
}

__device__ __forceinline__ unsigned int ord_f32(float f) {
    unsigned int u = __float_as_uint(f);
    return (u & 0x80000000u) ? ~u : (u | 0x80000000u);
}

__global__ __launch_bounds__(NTHREADS, 3)
void sagpool_kernel(const float* __restrict__ x,
                    const void*  __restrict__ edge_index,
                    const float* __restrict__ Wp,
                    const float* __restrict__ bp,
                    float* __restrict__ out,
                    long long E, int epg,
                    size_t off_ei, size_t off_keep, size_t off_batch,
                    size_t off_perm, size_t off_score)
{
    extern __shared__ char smem[];
    // ---- layout (must match host sizing) ----
    float* wsh   = (float*)smem;                       // 256
    float* h_s   = wsh + CC;                           // 288
    float* dis_s = h_s + 288;                          // 288
    float* sc_s  = dis_s + 288;                        // 288
    int* indeg_s = (int*)(sc_s + 288);                 // 288
    int* start_s = indeg_s + 288;                      // 288
    int* newid_s = start_s + 288;                      // 288
    unsigned long long* keys = (unsigned long long*)(newid_s + 288); // 512
    unsigned int* ed = (unsigned int*)(keys + SORTN);  // epg u32
    unsigned short* ssrc = (unsigned short*)(ed + epg);// epg u16
    int* hist = (int*)((char*)ssrc + (((size_t)epg * 2 + 15) & ~(size_t)15)); // 8*HB

    const int tid  = threadIdx.x;
    const int lane = tid & 31;
    const int warp = tid >> 5;
    const int g    = blockIdx.x;
    const long long gbase = (long long)g * RR;
    const int is64 = g_edge_is64;

    // ---- stage W, init small arrays ----
    if (tid < CC) wsh[tid] = Wp[tid];
    for (int v = tid; v < RR; v += NTHREADS) newid_s[v] = -1;
    __syncthreads();

    // ---- phase A: h[v] as Eigen NEON row-major gemv (evalGemv path):
    //      one 4-lane packet accumulator, pmadd = vfmaq (fused FMA),
    //      predux: (a0+a2)+(a1+a3).  Direct gmem row loads, no staging.
    {
        const float4* w4 = (const float4*)wsh;
        {
            int row = tid;            // always < RR (256 < 273)
            const float4* xr = (const float4*)(x + ((size_t)(gbase + row)) * CC);
            float a0 = 0.f, a1 = 0.f, a2 = 0.f, a3 = 0.f;
            #pragma unroll 4
            for (int i = 0; i < 64; i++) {
                float4 v = xr[i];
                float4 w = w4[i];
                a0 = fmaf(v.x, w.x, a0);
                a1 = fmaf(v.y, w.y, a1);
                a2 = fmaf(v.z, w.z, a2);
                a3 = fmaf(v.w, w.w, a3);
            }
            h_s[row] = __fadd_rn(__fadd_rn(a0, a2), __fadd_rn(a1, a3));
        }
        int row2 = tid + NTHREADS;
        if (row2 < RR) {
            const float4* xr = (const float4*)(x + ((size_t)(gbase + row2)) * CC);
            float a0 = 0.f, a1 = 0.f, a2 = 0.f, a3 = 0.f;
            #pragma unroll 4
            for (int i = 0; i < 64; i++) {
                float4 v = xr[i];
                float4 w = w4[i];
                a0 = fmaf(v.x, w.x, a0);
                a1 = fmaf(v.y, w.y, a1);
                a2 = fmaf(v.z, w.z, a2);
                a3 = fmaf(v.w, w.w, a3);
            }
            h_s[row2] = __fadd_rn(__fadd_rn(a0, a2), __fadd_rn(a1, a3));
        }
    }

    // ---- load edges -> packed local ids (src<<16 | dst) ----
    {
        const long long ebase = (long long)g * epg;
        if (is64) {
            const long long* p = (const long long*)edge_index;
            for (int e = tid; e < epg; e += NTHREADS) {
                int ls = (int)(p[ebase + e] - gbase);
                int ld = (int)(p[ebase + E + e] - gbase);
                ed[e] = ((unsigned)ls << 16) | (unsigned)ld;
            }
        } else {
            const int* p = (const int*)edge_index;
            for (int e = tid; e < epg; e += NTHREADS) {
                int ls = (int)(p[ebase + e] - gbase);
                int ld = (int)(p[ebase + E + e] - gbase);
                ed[e] = ((unsigned)ls << 16) | (unsigned)ld;
            }
        }
    }

    // ---- stable counting sort of edges by dst ----
    for (int i = tid; i < NWARPS * HB; i += NTHREADS) hist[i] = 0;
    __syncthreads();   // h_s, ed, hist all ready

    const int per = (((epg + NWARPS - 1) / NWARPS) + 31) & ~31;
    const int cbeg = warp * per;
    const int cend = min(epg, cbeg + per);

    // pass 1: per-warp-chunk histograms
    for (int base = cbeg; base < cend; base += 32) {
        int e = base + lane;
        bool act = e < cend;
        unsigned v = act ? ed[e] : 0u;
        int dst = act ? (int)(v & 0xFFFFu) : (512 + lane);
        unsigned m = __match_any_sync(FULLM, dst);
        int leader = __ffs(m) - 1;
        if (act && lane == leader) hist[warp * HB + dst] += __popc(m);
        __syncwarp();
    }
    __syncthreads();

    // in-degree, dis = 1/sqrt(deg) (deg includes self-loop), both correctly rounded
    for (int v = tid; v < RR; v += NTHREADS) {
        int s = 0;
        #pragma unroll
        for (int w2 = 0; w2 < NWARPS; w2++) s += hist[w2 * HB + v];
        indeg_s[v] = s;
        dis_s[v] = __fdiv_rn(1.0f, __fsqrt_rn((float)(s + 1)));
    }
    __syncthreads();

    // exclusive scan of indeg -> start offsets (warp 0)
    if (warp == 0) {
        int lo = lane * 9;
        int acc = 0;
        #pragma unroll
        for (int i = 0; i < 9; i++) { int v = lo + i; if (v < RR) acc += indeg_s[v]; }
        int ex = acc;
        #pragma unroll
        for (int o = 1; o < 32; o <<= 1) {
            int t = __shfl_up_sync(FULLM, ex, o);
            if (lane >= o) ex += t;
        }
        ex -= acc;
        int run = ex;
        #pragma unroll
        for (int i = 0; i < 9; i++) {
            int v = lo + i;
            if (v < RR) { start_s[v] = run; run += indeg_s[v]; }
        }
    }
    __syncthreads();

    // per-(warp,dst) base pointers (in place)
    for (int v = tid; v < RR; v += NTHREADS) {
        int s = start_s[v];
        #pragma unroll
        for (int w2 = 0; w2 < NWARPS; w2++) {
            int t = hist[w2 * HB + v];
            hist[w2 * HB + v] = s;
            s += t;
        }
    }
    __syncthreads();

    // pass 2: stable placement of src ids into per-dst lists
    for (int base = cbeg; base < cend; base += 32) {
        int e = base + lane;
        bool act = e < cend;
        unsigned v = act ? ed[e] : 0u;
        int dst = act ? (int)(v & 0xFFFFu) : (512 + lane);
        unsigned m = __match_any_sync(FULLM, dst);
        int rank = __popc(m & ((1u << lane) - 1u));
        int pos = 0;
        if (act) pos = hist[warp * HB + dst] + rank;
        __syncwarp();
        if (act) ssrc[pos] = (unsigned short)(v >> 16);
        int leader = __ffs(m) - 1;
        if (act && lane == leader) hist[warp * HB + dst] += __popc(m);
        __syncwarp();
    }
    __syncthreads();

    // ---- score: strictly sequential in reference scatter order ----
    const float bval = bp[0];
    for (int v = tid; v < RR; v += NTHREADS) {
        float dv = dis_s[v];
        float acc = 0.f;
        int st = start_s[v], n = indeg_s[v];
        for (int i = 0; i < n; i++) {
            int src = ssrc[st + i];
            float c = __fmul_rn(__fmul_rn(dis_s[src], dv), h_s[src]);
            acc = __fadd_rn(acc, c);
        }
        float selfc = __fmul_rn(__fmul_rn(dv, dv), h_s[v]);
        acc = __fadd_rn(acc, selfc);
        float sc = __fadd_rn(acc, bval);
        sc_s[v] = sc;
        out[off_score + (size_t)gbase + v] = sc;
    }
    __syncthreads();

    // ---- sort keys ----
    for (int v = tid; v < SORTN; v += NTHREADS) {
        if (v < RR) {
            keys[v] = ((unsigned long long)ord_f32(sc_s[v]) << 32)
                      | (unsigned long long)(0x1FFu - (unsigned)v);
        } else keys[v] = 0ull;
    }

    // bitonic sort descending (ties -> lower index first)
    for (int kk = 2; kk <= SORTN; kk <<= 1) {
        for (int j = kk >> 1; j > 0; j >>= 1) {
            __syncthreads();
            for (int t = tid; t < SORTN; t += NTHREADS) {
                int ixj = t ^ j;
                if (ixj > t) {
                    bool desc = ((t & kk) == 0);
                    unsigned long long a = keys[t], b2 = keys[ixj];
                    if ((a < b2) == desc) { keys[t] = b2; keys[ixj] = a; }
                }
            }
        }
    }
    __syncthreads();

    // ---- new-id map ----
    if (tid < KK) {
        int v = 0x1FF - (int)(keys[tid] & 0xFFFFFFFFull);
        newid_s[v] = tid;
    }
    __syncthreads();

    // ---- x_new / perm / batch_new ----
    for (int k = warp; k < KK; k += NWARPS) {
        int v = 0x1FF - (int)(keys[k] & 0xFFFFFFFFull);
        float t = tanhf(sc_s[v]);
        const float4* srcp = (const float4*)(x + ((size_t)(gbase + v)) * CC);
        float4* dstp = (float4*)(out + ((size_t)g * KK + k) * CC);
        #pragma unroll
        for (int j = 0; j < 2; j++) {
            float4 a = srcp[lane + 32 * j];
            a.x *= t; a.y *= t; a.z *= t; a.w *= t;
            dstp[lane + 32 * j] = a;
        }
        if (lane == 0) {
            out[off_perm  + (size_t)g * KK + k] = (float)(gbase + v);
            out[off_batch + (size_t)g * KK + k] = (float)g;
        }
    }

    // ---- edge remap + keep ----
    {
        const size_t ebase = (size_t)g * epg;
        const int gk = g * KK;
        for (int e = tid; e < epg; e += NTHREADS) {
            unsigned v = ed[e];
            int ns = newid_s[v >> 16];
            int nd = newid_s[v & 0xFFFFu];
            size_t ge = ebase + e;
            if (ns >= 0 && nd >= 0) {
                out[off_ei + ge]             = (float)(gk + ns);
                out[off_ei + (size_t)E + ge] = (float)(gk + nd);
                out[off_keep + ge]           = 1.0f;
            } else {
                out[off_ei + ge]             = -1.0f;
                out[off_ei + (size_t)E + ge] = -1.0f;
                out[off_keep + ge]           = 0.0f;
            }
        }
    }
}

extern "C" void kernel_launch(void* const* d_in, const int* in_sizes, int n_in,
                              void* d_out, int out_size)
{
    const float* x  = (const float*)d_in[0];
    const void*  ei = d_in[1];
    const float* W  = (const float*)d_in[3];
    const float* b  = (const float*)d_in[4];

    long long N = (long long)in_sizes[0] / CC;
    long long E = (long long)in_sizes[1] / 2;
    int G   = (int)(N / RR);
    int epg = (int)(E / G);

    float* out = (float*)d_out;
    size_t GK        = (size_t)G * KK;
    size_t off_ei    = GK * CC;
    size_t off_keep  = off_ei + 2 * (size_t)E;
    size_t off_batch = off_keep + (size_t)E;
    size_t off_perm  = off_batch + GK;
    size_t off_score = off_perm + GK;

    // dynamic smem size (must match kernel layout)
    size_t fixed = (size_t)CC * 4 + 6 * 288 * 4 + (size_t)SORTN * 8;
    size_t edB   = (size_t)epg * 4;
    size_t ssrcB = (((size_t)epg * 2 + 15) & ~(size_t)15);
    size_t histB = (size_t)NWARPS * HB * 4;
    size_t smemB = fixed + edB + ssrcB + histB + 64;

    static int attr_set = 0;
    if (!attr_set) {
        cudaFuncSetAttribute(sagpool_kernel,
                             cudaFuncAttributeMaxDynamicSharedMemorySize,
                             (int)smemB);
        attr_set = 1;
    }

    probe_dtype_kernel<<<1, 32>>>((const int*)ei);
    sagpool_kernel<<<G, NTHREADS, smemB>>>(x, ei, W, b, out, E, epg,
                                           off_ei, off_keep, off_batch,
                                           off_perm, off_score);
}